// round 9
// baseline (speedup 1.0000x reference)
#include <cuda_runtime.h>
#include <math.h>

#define B       64
#define T_ENC   1024
#define D_ENC   512
#define Q_DIM   1024
#define H       256
#define M       5
#define EPSC    1e-5f
#define KSPLIT  32
#define KB      (Q_DIM / KSPLIT)   // 32 k per GEMM block
#define NBLK    512
#define CH_ROWS 32
#define NCHUNK  (B * T_ENC / CH_ROWS)   // 2048

// Scratch (no allocation allowed -> __device__ globals)
__device__ float    g_hp[KSPLIT * B * H];   // GEMM1 partials (2 MB)
__device__ unsigned g_cnt;                  // barrier counter (monotonic)
__device__ unsigned g_wrk;                  // work-steal ticket (reset in P1)

__device__ __forceinline__ float softplusf(float v)
{
    return (v > 20.f) ? v : log1pf(expf(v));
}

// Monotonic-counter grid barrier (replay-safe; round = count/NBLK).
// All 512 CTAs co-resident: launch_bounds(256,4) -> >=528 slots even in the
// worst 132-SM occ-4 placement.
__device__ __forceinline__ void grid_barrier()
{
    __syncthreads();
    if (threadIdx.x == 0) {
        __threadfence();
        unsigned my     = atomicAdd(&g_cnt, 1u);
        unsigned target = (my / NBLK + 1u) * NBLK;
        while ((int)(*(volatile unsigned*)&g_cnt - target) < 0)
            __nanosleep(64);
        __threadfence();
    }
    __syncthreads();
}

__global__ void __launch_bounds__(256, 4)
fused_mol(const float* __restrict__ x,
          const float* __restrict__ memory,
          const unsigned char* __restrict__ mask,
          const float* __restrict__ mu_prev,
          const float* __restrict__ W1,
          const float* __restrict__ b1,
          const float* __restrict__ W2,
          const float* __restrict__ b2,
          float* __restrict__ out_ctx,
          float* __restrict__ out_alpha)
{
    __shared__ float  xs[8][KB];        // P1: x tile
    __shared__ float  hs[H];            // P2: hidden acts
    __shared__ float  sp[16];           // P2: raw params
    __shared__ float  smix[3][M];       // P2: w / inv_sigma / mu
    __shared__ float  sal[CH_ROWS];     // P3: alpha rows of current chunk
    __shared__ float4 red[128];         // P3: half-combine
    __shared__ int    s_t[2];           // P3: ticket double buffer

    const int blk = blockIdx.x;
    const int tid = threadIdx.x;

    // ======================= Phase 1: GEMM1 partials =======================
    if (blk < 256) {
        const int bbk   = blk >> 5;          // batch chunk (8 batches)
        const int kz    = blk & 31;          // k slice (32 k)
        const int cq    = tid & 63;          // col quad
        const int bp    = tid >> 6;          // 0..3 -> batches {2bp,2bp+1}
        const int bbase = bbk * 8;
        const int kbase = kz * KB;

        xs[tid >> 5][tid & 31] =
            x[(bbase + (tid >> 5)) * Q_DIM + kbase + (tid & 31)];
        __syncthreads();

        float4 acc0 = make_float4(0.f, 0.f, 0.f, 0.f);
        float4 acc1 = make_float4(0.f, 0.f, 0.f, 0.f);
        const float4* wp = (const float4*)(W1 + (size_t)kbase * H) + cq;

        #pragma unroll
        for (int g = 0; g < 4; g++) {
            float4 wv[8];
            #pragma unroll
            for (int k = 0; k < 8; k++)
                wv[k] = wp[(size_t)(g * 8 + k) * (H / 4)];
            #pragma unroll
            for (int k = 0; k < 8; k++) {
                float x0 = xs[bp * 2 + 0][g * 8 + k];
                float x1 = xs[bp * 2 + 1][g * 8 + k];
                acc0.x = fmaf(x0, wv[k].x, acc0.x);
                acc0.y = fmaf(x0, wv[k].y, acc0.y);
                acc0.z = fmaf(x0, wv[k].z, acc0.z);
                acc0.w = fmaf(x0, wv[k].w, acc0.w);
                acc1.x = fmaf(x1, wv[k].x, acc1.x);
                acc1.y = fmaf(x1, wv[k].y, acc1.y);
                acc1.z = fmaf(x1, wv[k].z, acc1.z);
                acc1.w = fmaf(x1, wv[k].w, acc1.w);
            }
        }

        float4* hp = (float4*)(g_hp + (size_t)kz * (B * H));
        hp[(size_t)(bbase + bp * 2 + 0) * (H / 4) + cq] = acc0;
        hp[(size_t)(bbase + bp * 2 + 1) * (H / 4) + cq] = acc1;
    } else if (blk < 320) {
        const int b0 = blk - 256;
        out_ctx[b0 * D_ENC + tid]       = 0.f;
        out_ctx[b0 * D_ENC + tid + 256] = 0.f;
        if (blk == 256 && tid == 0) g_wrk = 0u;   // reset ticket (replay-safe)
    }

    grid_barrier();   // ========== barrier 1 ==========

    // ============ Phase 2: params + alpha (64 CTAs, 1 per batch) ===========
    if (blk < B) {
        const int b    = blk;
        const int wid  = tid >> 5;
        const int lane = tid & 31;

        float a[8];
        #pragma unroll
        for (int i = 0; i < 8; i++) a[i] = 0.f;
        const float* hpb = g_hp + b * H + tid;
        #pragma unroll
        for (int s = 0; s < KSPLIT; s += 8) {
            #pragma unroll
            for (int i = 0; i < 8; i++)
                a[i] += hpb[(size_t)(s + i) * (B * H)];
        }
        float v = ((a[0] + a[1]) + (a[2] + a[3])) +
                  ((a[4] + a[5]) + (a[6] + a[7]));
        hs[tid] = fmaxf(v + b1[tid], 0.f);
        __syncthreads();

        for (int j = wid; j < 3 * M; j += 8) {
            float s = 0.f;
            #pragma unroll
            for (int k = lane; k < H; k += 32)
                s = fmaf(hs[k], W2[k * (3 * M) + j], s);
            #pragma unroll
            for (int o = 16; o; o >>= 1)
                s += __shfl_down_sync(0xffffffffu, s, o);
            if (lane == 0) sp[j] = s + b2[j];
        }
        __syncthreads();

        if (tid == 0) {
            float mx = sp[0];
            #pragma unroll
            for (int m = 1; m < M; m++) mx = fmaxf(mx, sp[m]);
            float e[M], se = 0.f;
            #pragma unroll
            for (int m = 0; m < M; m++) { e[m] = expf(sp[m] - mx); se += e[m]; }
            float inv = 1.f / se;
            #pragma unroll
            for (int m = 0; m < M; m++) {
                smix[0][m] = e[m] * inv + EPSC;
                smix[1][m] = 1.f / (softplusf(sp[M + m]) + EPSC);
                smix[2][m] = mu_prev[b * M + m] + softplusf(sp[2 * M + m]);
            }
        }
        __syncthreads();

        float w[M], is[M], mu[M];
        #pragma unroll
        for (int m = 0; m < M; m++) {
            w[m]  = smix[0][m];
            is[m] = smix[1][m];
            mu[m] = smix[2][m];
        }
        #pragma unroll
        for (int i = 0; i < 4; i++) {
            const int t = tid + i * 256;
            const float jv0 = (float)t + 0.5f;
            const float jv1 = (float)t + 1.5f;
            float al = 0.f;
            #pragma unroll
            for (int m = 0; m < M; m++) {
                float z0 = (mu[m] - jv0) * is[m];
                float z1 = (mu[m] - jv1) * is[m];
                float s0 = 1.f / (1.f + __expf(-z0));
                float s1 = 1.f / (1.f + __expf(-z1));
                al += w[m] * (1.f / (1.f + s1) - 1.f / (1.f + s0));
            }
            if (al == 0.f) al = EPSC;
            if (mask[b * T_ENC + t]) al = 0.f;
            out_alpha[b * T_ENC + t] = al;
        }
    }

    grid_barrier();   // ========== barrier 2 ==========

    // ========= Phase 3: context streaming, work-stealing chunks ===========
    const int col  = tid & 127;          // float4 column
    const int half = tid >> 7;           // 0/1 -> 16 rows each

    float4 acc[4];
    #pragma unroll
    for (int i = 0; i < 4; i++) acc[i] = make_float4(0.f, 0.f, 0.f, 0.f);
    int cur_b = -1;

    if (tid == 0) s_t[0] = (int)atomicAdd(&g_wrk, 1u);
    __syncthreads();

    int pty = 0;
    for (;;) {
        const int c = s_t[pty];
        if (c >= NCHUNK) break;
        const int cb = c >> 5;                 // batch
        const int rb = (c & 31) * CH_ROWS;     // row base

        if (cb != cur_b) {                     // flush previous batch (uniform)
            if (cur_b >= 0) {
                float4 s4 = make_float4(
                    acc[0].x + acc[1].x + acc[2].x + acc[3].x,
                    acc[0].y + acc[1].y + acc[2].y + acc[3].y,
                    acc[0].z + acc[1].z + acc[2].z + acc[3].z,
                    acc[0].w + acc[1].w + acc[2].w + acc[3].w);
                __syncthreads();               // prior red reads done
                if (half == 1) red[col] = s4;
                __syncthreads();
                if (half == 0) {
                    float4 o = red[col];
                    float* cp = out_ctx + cur_b * D_ENC + col * 4;
                    atomicAdd(cp + 0, s4.x + o.x);
                    atomicAdd(cp + 1, s4.y + o.y);
                    atomicAdd(cp + 2, s4.z + o.z);
                    atomicAdd(cp + 3, s4.w + o.w);
                }
                #pragma unroll
                for (int i = 0; i < 4; i++)
                    acc[i] = make_float4(0.f, 0.f, 0.f, 0.f);
            }
            cur_b = cb;
        }

        if (tid == 0) s_t[pty ^ 1] = (int)atomicAdd(&g_wrk, 1u);
        float av_ld = 0.f;
        if (tid < CH_ROWS) av_ld = out_alpha[cb * T_ENC + rb + tid];
        __syncthreads();                       // prior sal reads done
        if (tid < CH_ROWS) sal[tid] = av_ld;
        __syncthreads();                       // sal + next ticket ready

        const float4* mp = (const float4*)memory +
            ((size_t)cb * T_ENC + rb + half * 16) * (D_ENC / 4) + col;

        #pragma unroll
        for (int r = 0; r < 16; r += 8) {
            float4 v[8];
            #pragma unroll
            for (int u = 0; u < 8; u++)
                v[u] = mp[(size_t)(r + u) * (D_ENC / 4)];
            #pragma unroll
            for (int u = 0; u < 8; u++) {
                float av = sal[half * 16 + r + u];
                float4& a4 = acc[u & 3];
                a4.x = fmaf(av, v[u].x, a4.x);
                a4.y = fmaf(av, v[u].y, a4.y);
                a4.z = fmaf(av, v[u].z, a4.z);
                a4.w = fmaf(av, v[u].w, a4.w);
            }
        }
        pty ^= 1;
    }

    // final flush
    if (cur_b >= 0) {
        float4 s4 = make_float4(
            acc[0].x + acc[1].x + acc[2].x + acc[3].x,
            acc[0].y + acc[1].y + acc[2].y + acc[3].y,
            acc[0].z + acc[1].z + acc[2].z + acc[3].z,
            acc[0].w + acc[1].w + acc[2].w + acc[3].w);
        __syncthreads();
        if (half == 1) red[col] = s4;
        __syncthreads();
        if (half == 0) {
            float4 o = red[col];
            float* cp = out_ctx + cur_b * D_ENC + col * 4;
            atomicAdd(cp + 0, s4.x + o.x);
            atomicAdd(cp + 1, s4.y + o.y);
            atomicAdd(cp + 2, s4.z + o.z);
            atomicAdd(cp + 3, s4.w + o.w);
        }
    }
}

// ---------------------------------------------------------------------------
extern "C" void kernel_launch(void* const* d_in, const int* in_sizes, int n_in,
                              void* d_out, int out_size)
{
    const float*         x       = (const float*)d_in[0];
    const float*         memory  = (const float*)d_in[1];
    const unsigned char* mask    = (const unsigned char*)d_in[2];
    const float*         mu_prev = (const float*)d_in[3];
    const float*         W1      = (const float*)d_in[4];
    const float*         b1      = (const float*)d_in[5];
    const float*         W2      = (const float*)d_in[6];
    const float*         b2      = (const float*)d_in[7];

    float* out       = (float*)d_out;
    float* out_ctx   = out;                 // [B, D_ENC]
    float* out_alpha = out + B * D_ENC;     // [B, T_ENC]

    fused_mol<<<NBLK, 256>>>(x, memory, mask, mu_prev,
                             W1, b1, W2, b2, out_ctx, out_alpha);
}

// round 10
// speedup vs baseline: 1.0925x; 1.0925x over previous
#include <cuda_runtime.h>
#include <math.h>

#define B       64
#define T_ENC   1024
#define D_ENC   512
#define Q_DIM   1024
#define H       256
#define M       5
#define EPSC    1e-5f
#define KSPLIT  64
#define KB      (Q_DIM / KSPLIT)   // 16 k per GEMM block
#define NBLK    1024

// Scratch (no allocation allowed -> __device__ globals)
__device__ float    g_hp[KSPLIT * B * H];   // GEMM1 partials (4 MB)
__device__ unsigned g_cnt;                  // barrier counter (monotonic)

__device__ __forceinline__ float softplusf(float v)
{
    return (v > 20.f) ? v : log1pf(expf(v));
}

// Monotonic-counter grid barrier (replay-safe; round = count/NBLK).
// Co-residency: launch_bounds(128,8) -> 8 CTAs/SM * 148 = 1184 >= 1024.
__device__ __forceinline__ void grid_barrier()
{
    __syncthreads();
    if (threadIdx.x == 0) {
        __threadfence();
        unsigned my     = atomicAdd(&g_cnt, 1u);
        unsigned target = (my / NBLK + 1u) * NBLK;
        while ((int)(*(volatile unsigned*)&g_cnt - target) < 0)
            __nanosleep(64);
        __threadfence();
    }
    __syncthreads();
}

__global__ void __launch_bounds__(128, 8)
fused_mol(const float* __restrict__ x,
          const float* __restrict__ memory,
          const unsigned char* __restrict__ mask,
          const float* __restrict__ mu_prev,
          const float* __restrict__ W1,
          const float* __restrict__ b1,
          const float* __restrict__ W2,
          const float* __restrict__ b2,
          float* __restrict__ out_ctx,
          float* __restrict__ out_alpha)
{
    __shared__ float xs[8][KB];     // P1: x tile (512 B)
    __shared__ float hs[H];         // P2: hidden acts
    __shared__ float sp[16];        // P2: raw params
    __shared__ float smix[3][M];    // P2: w / inv_sigma / mu
    __shared__ float sal[64];       // P3: alpha rows

    const int blk = blockIdx.x;
    const int tid = threadIdx.x;

    // ======================= Phase 1: GEMM1 partials =======================
    // 512 CTAs: blk = bbk*64 + kz. 128 thr = 64 col-quads x 2 batch-quads
    // (4 batches each). KB=16 -> two 8-deep LDG.128 waves.
    if (blk < 512) {
        const int bbk   = blk >> 6;          // batch chunk (8 batches)
        const int kz    = blk & 63;          // k slice (16 k)
        const int cq    = tid & 63;          // col quad: cols 4*cq..+3
        const int bp    = tid >> 6;          // 0..1 -> batches bp*4..+3
        const int bbase = bbk * 8;
        const int kbase = kz * KB;

        xs[tid >> 4][tid & 15] =
            x[(bbase + (tid >> 4)) * Q_DIM + kbase + (tid & 15)];
        __syncthreads();

        float4 acc[4];
        #pragma unroll
        for (int i = 0; i < 4; i++) acc[i] = make_float4(0.f, 0.f, 0.f, 0.f);
        const float4* wp = (const float4*)(W1 + (size_t)kbase * H) + cq;

        #pragma unroll
        for (int g = 0; g < 2; g++) {
            float4 wv[8];                        // 8 LDG.128 in flight
            #pragma unroll
            for (int k = 0; k < 8; k++)
                wv[k] = wp[(size_t)(g * 8 + k) * (H / 4)];
            #pragma unroll
            for (int k = 0; k < 8; k++) {
                #pragma unroll
                for (int i = 0; i < 4; i++) {
                    float xb = xs[bp * 4 + i][g * 8 + k];
                    acc[i].x = fmaf(xb, wv[k].x, acc[i].x);
                    acc[i].y = fmaf(xb, wv[k].y, acc[i].y);
                    acc[i].z = fmaf(xb, wv[k].z, acc[i].z);
                    acc[i].w = fmaf(xb, wv[k].w, acc[i].w);
                }
            }
        }

        float4* hp = (float4*)(g_hp + (size_t)kz * (B * H));
        #pragma unroll
        for (int i = 0; i < 4; i++)
            hp[(size_t)(bbase + bp * 4 + i) * (H / 4) + cq] = acc[i];
    } else if (blk < 576) {
        // zero out_ctx: one batch row per CTA (512 floats / 128 thr)
        const int b0 = blk - 512;
        ((float4*)(out_ctx + b0 * D_ENC))[tid] =
            make_float4(0.f, 0.f, 0.f, 0.f);
    }

    grid_barrier();   // ========== barrier 1 ==========

    // ============ Phase 2: params + alpha (64 CTAs, 1 per batch) ===========
    if (blk < B) {
        const int b    = blk;
        const int wid  = tid >> 5;
        const int lane = tid & 31;

        // reduce 64 partials for h elements tid and tid+128
        #pragma unroll
        for (int e = 0; e < 2; e++) {
            const int hi = tid + e * 128;
            float a[8];
            #pragma unroll
            for (int i = 0; i < 8; i++) a[i] = 0.f;
            const float* hpb = g_hp + b * H + hi;
            #pragma unroll
            for (int s = 0; s < KSPLIT; s += 8) {
                #pragma unroll
                for (int i = 0; i < 8; i++)
                    a[i] += hpb[(size_t)(s + i) * (B * H)];
            }
            float v = ((a[0] + a[1]) + (a[2] + a[3])) +
                      ((a[4] + a[5]) + (a[6] + a[7]));
            hs[hi] = fmaxf(v + b1[hi], 0.f);
        }
        __syncthreads();

        for (int j = wid; j < 3 * M; j += 4) {
            float s = 0.f;
            #pragma unroll
            for (int k = lane; k < H; k += 32)
                s = fmaf(hs[k], W2[k * (3 * M) + j], s);
            #pragma unroll
            for (int o = 16; o; o >>= 1)
                s += __shfl_down_sync(0xffffffffu, s, o);
            if (lane == 0) sp[j] = s + b2[j];
        }
        __syncthreads();

        if (tid == 0) {
            float mx = sp[0];
            #pragma unroll
            for (int m = 1; m < M; m++) mx = fmaxf(mx, sp[m]);
            float e[M], se = 0.f;
            #pragma unroll
            for (int m = 0; m < M; m++) { e[m] = expf(sp[m] - mx); se += e[m]; }
            float inv = 1.f / se;
            #pragma unroll
            for (int m = 0; m < M; m++) {
                smix[0][m] = e[m] * inv + EPSC;
                smix[1][m] = 1.f / (softplusf(sp[M + m]) + EPSC);
                smix[2][m] = mu_prev[b * M + m] + softplusf(sp[2 * M + m]);
            }
        }
        __syncthreads();

        float w[M], is[M], mu[M];
        #pragma unroll
        for (int m = 0; m < M; m++) {
            w[m]  = smix[0][m];
            is[m] = smix[1][m];
            mu[m] = smix[2][m];
        }
        #pragma unroll
        for (int i = 0; i < 8; i++) {
            const int t = tid + i * 128;
            const float jv0 = (float)t + 0.5f;
            const float jv1 = (float)t + 1.5f;
            float al = 0.f;
            #pragma unroll
            for (int m = 0; m < M; m++) {
                float z0 = (mu[m] - jv0) * is[m];
                float z1 = (mu[m] - jv1) * is[m];
                float s0 = 1.f / (1.f + __expf(-z0));
                float s1 = 1.f / (1.f + __expf(-z1));
                al += w[m] * (1.f / (1.f + s1) - 1.f / (1.f + s0));
            }
            if (al == 0.f) al = EPSC;
            if (mask[b * T_ENC + t]) al = 0.f;
            out_alpha[b * T_ENC + t] = al;
        }
    }

    grid_barrier();   // ========== barrier 2 ==========

    // ============== Phase 3: context streaming (all 1024 CTAs) =============
    // blk -> (batch, 64-row chunk); 128 thr = one float4 column each.
    {
        const int b    = blk >> 4;
        const int base = (blk & 15) * 64;

        if (tid < 64) sal[tid] = out_alpha[b * T_ENC + base + tid];
        __syncthreads();

        float4 acc[2];
        acc[0] = make_float4(0.f, 0.f, 0.f, 0.f);
        acc[1] = make_float4(0.f, 0.f, 0.f, 0.f);

        const float4* mp = (const float4*)memory +
            ((size_t)b * T_ENC + base) * (D_ENC / 4) + tid;

        #pragma unroll
        for (int r = 0; r < 64; r += 8) {
            float4 v[8];
            #pragma unroll
            for (int u = 0; u < 8; u++)
                v[u] = __ldcs(&mp[(size_t)(r + u) * (D_ENC / 4)]);
            #pragma unroll
            for (int u = 0; u < 8; u++) {
                float av = sal[r + u];
                float4& a4 = acc[u & 1];
                a4.x = fmaf(av, v[u].x, a4.x);
                a4.y = fmaf(av, v[u].y, a4.y);
                a4.z = fmaf(av, v[u].z, a4.z);
                a4.w = fmaf(av, v[u].w, a4.w);
            }
        }
        acc[0].x += acc[1].x;
        acc[0].y += acc[1].y;
        acc[0].z += acc[1].z;
        acc[0].w += acc[1].w;

        float* c = out_ctx + b * D_ENC + tid * 4;
        atomicAdd(c + 0, acc[0].x);
        atomicAdd(c + 1, acc[0].y);
        atomicAdd(c + 2, acc[0].z);
        atomicAdd(c + 3, acc[0].w);
    }
}

// ---------------------------------------------------------------------------
extern "C" void kernel_launch(void* const* d_in, const int* in_sizes, int n_in,
                              void* d_out, int out_size)
{
    const float*         x       = (const float*)d_in[0];
    const float*         memory  = (const float*)d_in[1];
    const unsigned char* mask    = (const unsigned char*)d_in[2];
    const float*         mu_prev = (const float*)d_in[3];
    const float*         W1      = (const float*)d_in[4];
    const float*         b1      = (const float*)d_in[5];
    const float*         W2      = (const float*)d_in[6];
    const float*         b2      = (const float*)d_in[7];

    float* out       = (float*)d_out;
    float* out_ctx   = out;                 // [B, D_ENC]
    float* out_alpha = out + B * D_ENC;     // [B, T_ENC]

    fused_mol<<<NBLK, 128>>>(x, memory, mask, mu_prev,
                             W1, b1, W2, b2, out_ctx, out_alpha);
}

// round 11
// speedup vs baseline: 1.7135x; 1.5684x over previous
#include <cuda_runtime.h>
#include <math.h>

#define B       64
#define T_ENC   1024
#define D_ENC   512
#define Q_DIM   1024
#define H       256
#define M       5
#define EPSC    1e-5f
#define KSPLIT  32
#define KB      (Q_DIM / KSPLIT)   // 32 k per K1 block
#define NBLK    512
#define TCHUNK  128

// Scratch (no allocation allowed -> __device__ globals)
__device__ float    g_hp[KSPLIT * B * H];   // GEMM1 partials (2 MB)
__device__ unsigned g_cnt;                  // barrier counter (monotonic)

__device__ __forceinline__ float softplusf(float v)
{
    return (v > 20.f) ? v : log1pf(expf(v));
}

// Monotonic-counter grid barrier: replay-safe (counter never resets; the
// round is identified by count/NBLK). All NBLK CTAs are co-resident by
// construction (launch_bounds(256,4) -> 4 CTAs/SM * 148 = 592 >= 512).
__device__ __forceinline__ void grid_barrier()
{
    __syncthreads();
    if (threadIdx.x == 0) {
        __threadfence();
        unsigned my     = atomicAdd(&g_cnt, 1u);
        unsigned target = (my / NBLK + 1u) * NBLK;
        while ((int)(*(volatile unsigned*)&g_cnt - target) < 0)
            __nanosleep(64);
        __threadfence();
    }
    __syncthreads();
}

__global__ void __launch_bounds__(256, 4)
fused_mol(const float* __restrict__ x,
          const float* __restrict__ memory,
          const unsigned char* __restrict__ mask,
          const float* __restrict__ mu_prev,
          const float* __restrict__ W1,
          const float* __restrict__ b1,
          const float* __restrict__ W2,
          const float* __restrict__ b2,
          float* __restrict__ out_ctx,
          float* __restrict__ out_alpha)
{
    __shared__ float  xs[8][KB];        // P1: x tile (1 KB)
    __shared__ float  hs[H];            // P3: hidden acts
    __shared__ float  p[16];            // P3: raw params
    __shared__ float  salpha[TCHUNK];   // P3: alpha tile
    __shared__ float4 red[128];         // P3: half-combine

    const int blk = blockIdx.x;
    const int tid = threadIdx.x;

    // ======================= Phase 1: GEMM1 partials =======================
    if (blk < 256) {
        const int bbk   = blk >> 5;          // batch chunk (8 batches)
        const int kz    = blk & 31;          // k slice (32 k)
        const int cq    = tid & 63;          // col quad: cols 4*cq..+3
        const int bp    = tid >> 6;          // 0..3 -> batches {2bp, 2bp+1}
        const int bbase = bbk * 8;
        const int kbase = kz * KB;

        xs[tid >> 5][tid & 31] =
            x[(bbase + (tid >> 5)) * Q_DIM + kbase + (tid & 31)];
        __syncthreads();

        float4 acc0 = make_float4(0.f, 0.f, 0.f, 0.f);
        float4 acc1 = make_float4(0.f, 0.f, 0.f, 0.f);
        const float4* wp = (const float4*)(W1 + (size_t)kbase * H) + cq;

        #pragma unroll
        for (int g = 0; g < 4; g++) {
            float4 wv[8];                          // 8 LDG.128 in flight
            #pragma unroll
            for (int k = 0; k < 8; k++)
                wv[k] = wp[(size_t)(g * 8 + k) * (H / 4)];
            #pragma unroll
            for (int k = 0; k < 8; k++) {
                float x0 = xs[bp * 2 + 0][g * 8 + k];
                float x1 = xs[bp * 2 + 1][g * 8 + k];
                acc0.x = fmaf(x0, wv[k].x, acc0.x);
                acc0.y = fmaf(x0, wv[k].y, acc0.y);
                acc0.z = fmaf(x0, wv[k].z, acc0.z);
                acc0.w = fmaf(x0, wv[k].w, acc0.w);
                acc1.x = fmaf(x1, wv[k].x, acc1.x);
                acc1.y = fmaf(x1, wv[k].y, acc1.y);
                acc1.z = fmaf(x1, wv[k].z, acc1.z);
                acc1.w = fmaf(x1, wv[k].w, acc1.w);
            }
        }

        float4* hp = (float4*)(g_hp + (size_t)kz * (B * H));
        hp[(size_t)(bbase + bp * 2 + 0) * (H / 4) + cq] = acc0;
        hp[(size_t)(bbase + bp * 2 + 1) * (H / 4) + cq] = acc1;
    } else {
        // Idle half: zero out_ctx + prefetch the head 64KB of the two P3
        // chunks this CTA pair owns (chunks blk and blk-256) into L2, so the
        // P1/barrier/prologue window does useful DRAM work.
        if (blk < 320) {
            const int b0 = blk - 256;
            out_ctx[b0 * D_ENC + tid]       = 0.f;
            out_ctx[b0 * D_ENC + tid + 256] = 0.f;
        }
        #pragma unroll
        for (int i = 0; i < 2; i++) {
            const int c  = (i == 0) ? blk : (blk - 256);
            const int cb = c >> 3;
            const int rb = (c & 7) * TCHUNK;
            const char* pfb = (const char*)(memory +
                ((size_t)cb * T_ENC + rb) * D_ENC) + (size_t)tid * 128;
            asm volatile("prefetch.global.L2 [%0];" :: "l"(pfb));
            asm volatile("prefetch.global.L2 [%0];" :: "l"(pfb + 32768));
        }
    }

    // ============================ grid barrier =============================
    grid_barrier();

    // =============== Phase 2+3: params + alpha + context ===================
    const int b    = blk >> 3;           // batch
    const int base = (blk & 7) * TCHUNK; // t-chunk start
    const int wid  = tid >> 5;
    const int lane = tid & 31;

    // -- reduce GEMM1 partials + bias + relu -> hs (L2-hot, 8-way shared)
    {
        float a[8];
        #pragma unroll
        for (int i = 0; i < 8; i++) a[i] = 0.f;
        const float* hpb = g_hp + b * H + tid;
        #pragma unroll
        for (int s = 0; s < KSPLIT; s += 8) {
            #pragma unroll
            for (int i = 0; i < 8; i++)
                a[i] += hpb[(size_t)(s + i) * (B * H)];
        }
        float v = ((a[0] + a[1]) + (a[2] + a[3])) +
                  ((a[4] + a[5]) + (a[6] + a[7]));
        hs[tid] = fmaxf(v + b1[tid], 0.f);
    }
    __syncthreads();

    // -- params = hs @ W2 + b2 (8 warps cover 15 outputs in 2 rounds)
    for (int j = wid; j < 3 * M; j += 8) {
        float s = 0.f;
        #pragma unroll
        for (int k = lane; k < H; k += 32)
            s = fmaf(hs[k], W2[k * (3 * M) + j], s);
        #pragma unroll
        for (int o = 16; o; o >>= 1)
            s += __shfl_down_sync(0xffffffffu, s, o);
        if (lane == 0) p[j] = s + b2[j];
    }
    __syncthreads();

    // -- mixture transforms + alpha (threads 0..127, one t each)
    if (tid < TCHUNK) {
        float w[M], is[M], mu[M];
        {
            float mx = p[0];
            #pragma unroll
            for (int m = 1; m < M; m++) mx = fmaxf(mx, p[m]);
            float e[M], se = 0.f;
            #pragma unroll
            for (int m = 0; m < M; m++) { e[m] = expf(p[m] - mx); se += e[m]; }
            float inv = 1.f / se;
            #pragma unroll
            for (int m = 0; m < M; m++) {
                w[m]  = e[m] * inv + EPSC;
                is[m] = 1.f / (softplusf(p[M + m]) + EPSC);
                mu[m] = mu_prev[b * M + m] + softplusf(p[2 * M + m]);
            }
        }
        const int t = base + tid;
        const float jv0 = (float)t + 0.5f;
        const float jv1 = (float)t + 1.5f;
        float a = 0.f;
        #pragma unroll
        for (int m = 0; m < M; m++) {
            float z0 = (mu[m] - jv0) * is[m];
            float z1 = (mu[m] - jv1) * is[m];
            float s0 = 1.f / (1.f + __expf(-z0));
            float s1 = 1.f / (1.f + __expf(-z1));
            a += w[m] * (1.f / (1.f + s1) - 1.f / (1.f + s0));
        }
        if (a == 0.f) a = EPSC;
        if (mask[b * T_ENC + t]) a = 0.f;
        out_alpha[b * T_ENC + t] = a;
        salpha[tid] = a;
    }
    __syncthreads();

    // -- stream memory: 2 t-halves x 128 float4 cols, 8-deep load batching
    const int col  = tid & 127;
    const int half = tid >> 7;
    const int rbase = half * 64;

    float4 acc[4];
    #pragma unroll
    for (int i = 0; i < 4; i++) acc[i] = make_float4(0.f, 0.f, 0.f, 0.f);

    const float4* mp = (const float4*)memory +
        ((size_t)b * T_ENC + base + rbase) * (D_ENC / 4) + col;

    #pragma unroll
    for (int r = 0; r < 64; r += 8) {
        float4 v[8];
        #pragma unroll
        for (int u = 0; u < 8; u++)
            v[u] = mp[(size_t)(r + u) * (D_ENC / 4)];
        #pragma unroll
        for (int u = 0; u < 8; u++) {
            float av = salpha[rbase + r + u];
            float4& a4 = acc[u & 3];
            a4.x = fmaf(av, v[u].x, a4.x);
            a4.y = fmaf(av, v[u].y, a4.y);
            a4.z = fmaf(av, v[u].z, a4.z);
            a4.w = fmaf(av, v[u].w, a4.w);
        }
    }
    acc[0].x += acc[1].x + acc[2].x + acc[3].x;
    acc[0].y += acc[1].y + acc[2].y + acc[3].y;
    acc[0].z += acc[1].z + acc[2].z + acc[3].z;
    acc[0].w += acc[1].w + acc[2].w + acc[3].w;

    if (half == 1) red[col] = acc[0];
    __syncthreads();

    if (half == 0) {
        float4 o = red[col];
        float* c = out_ctx + b * D_ENC + col * 4;
        atomicAdd(c + 0, acc[0].x + o.x);
        atomicAdd(c + 1, acc[0].y + o.y);
        atomicAdd(c + 2, acc[0].z + o.z);
        atomicAdd(c + 3, acc[0].w + o.w);
    }
}

// ---------------------------------------------------------------------------
extern "C" void kernel_launch(void* const* d_in, const int* in_sizes, int n_in,
                              void* d_out, int out_size)
{
    const float*         x       = (const float*)d_in[0];
    const float*         memory  = (const float*)d_in[1];
    const unsigned char* mask    = (const unsigned char*)d_in[2];
    const float*         mu_prev = (const float*)d_in[3];
    const float*         W1      = (const float*)d_in[4];
    const float*         b1      = (const float*)d_in[5];
    const float*         W2      = (const float*)d_in[6];
    const float*         b2      = (const float*)d_in[7];

    float* out       = (float*)d_out;
    float* out_ctx   = out;                 // [B, D_ENC]
    float* out_alpha = out + B * D_ENC;     // [B, T_ENC]

    fused_mol<<<NBLK, 256>>>(x, memory, mask, mu_prev,
                             W1, b1, W2, b2, out_ctx, out_alpha);
}